// round 17
// baseline (speedup 1.0000x reference)
#include <cuda_runtime.h>
#include <cuda_fp16.h>
#include <cstdint>
#include <type_traits>

#define N_NODES 20000
#define HALF_N 10000
#define MAXC 256
#define SLOT_SHIFT 6               // 64 slots per node (max indeg; Poisson(16) tail ~e^-40)
#define SLOTS (1 << SLOT_SHIFT)

// ---------------- scratch ----------------
__device__ int    g_fill[N_NODES];                     // indeg after fill
__device__ float  g_dis[N_NODES];
__device__ int    g_slots[(size_t)N_NODES * SLOTS];    // src lists, fixed stride
__device__ __half g_h1[(size_t)N_NODES * MAXC];        // GEMM output, layers 1&3
__device__ __half g_h2[(size_t)N_NODES * MAXC];        // GEMM output, layer 2
__device__ __half g_t[(size_t)N_NODES * MAXC];         // layer activation (fp16)
__device__ __half g_xh[(size_t)N_NODES * MAXC];        // x converted to fp16
__device__ __half g_w1h[256 * 256];
__device__ __half g_w2h[256 * 128];
__device__ __half g_w3h[128 * 64];

// ---------------- prep ----------------
__global__ void zero_fill_kernel() {
    int i = blockIdx.x * blockDim.x + threadIdx.x;
    if (i < N_NODES) g_fill[i] = 0;
}

__global__ void fill_kernel(const int* __restrict__ ei, int E) {
    int e = blockIdx.x * blockDim.x + threadIdx.x;
    if (e < E) {
        int s = ei[e];
        int d = ei[E + e];
        int pos = atomicAdd(&g_fill[d], 1);
        g_slots[((size_t)d << SLOT_SHIFT) + pos] = s;
    }
}

__global__ void dis_kernel() {
    int i = blockIdx.x * blockDim.x + threadIdx.x;
    if (i < N_NODES) g_dis[i] = rsqrtf((float)g_fill[i] + 1.0f);   // +1 self-loop
}

// fp32 -> fp16, float4 granularity
__global__ void cvt_kernel(const float* __restrict__ in, __half* __restrict__ out, int n4) {
    int i = blockIdx.x * blockDim.x + threadIdx.x;
    if (i < n4) {
        float4 f = ((const float4*)in)[i];
        ((__half2*)out)[2 * i]     = __floats2half2_rn(f.x, f.y);
        ((__half2*)out)[2 * i + 1] = __floats2half2_rn(f.z, f.w);
    }
}

// ---------------- FP16 GEMM: 3-stage cp.async + ldmatrix + m16n8k16 ----------------
__device__ __forceinline__ uint32_t smem_u32(const void* p) {
    return (uint32_t)__cvta_generic_to_shared(p);
}

#define LDSM_X4(r0, r1, r2, r3, addr)                                        \
    asm volatile("ldmatrix.sync.aligned.m8n8.x4.shared.b16 {%0,%1,%2,%3}, [%4];" \
                 : "=r"(r0), "=r"(r1), "=r"(r2), "=r"(r3) : "r"(addr))

#define LDSM_X4_T(r0, r1, r2, r3, addr)                                      \
    asm volatile("ldmatrix.sync.aligned.m8n8.x4.trans.shared.b16 {%0,%1,%2,%3}, [%4];" \
                 : "=r"(r0), "=r"(r1), "=r"(r2), "=r"(r3) : "r"(addr))

__global__ void gemm_f16_kernel(const __half* __restrict__ A, const __half* __restrict__ B,
                                __half* __restrict__ Ch, int M, int N, int K) {
    const int BM = 128, BN = 64, BK = 16, ST = 3;
    const int ASTRIDE = 24;   // halves per A row (48B) -> conflict-free ldmatrix
    const int BSTRIDE = 72;   // halves per B k-row (144B) -> conflict-free ldmatrix.trans
    __shared__ __half As[ST][BM][ASTRIDE];
    __shared__ __half Bs[ST][BK][BSTRIDE];
    const int ABUF = BM * ASTRIDE * 2;
    const int BBUF = BK * BSTRIDE * 2;

    int tid = threadIdx.x;
    int lane = tid & 31;
    int wid = tid >> 5;
    int warp_m = wid & 3;
    int warp_n = wid >> 2;
    int brow = blockIdx.y * BM;
    int bcol = blockIdx.x * BN;

    int am = tid >> 1, aj = tid & 1;                // A: 16B per thread
    int bk = tid >> 4, bc = tid & 15;               // B: 8B per thread
    int agr = brow + am;
    const __half* aSrcBase = A + (size_t)agr * K + aj * 8;
    const __half* bSrcBase = B + (size_t)bk * N + bcol + bc * 4;
    uint32_t aDst = smem_u32(&As[0][0][0]) + am * 48 + aj * 16;
    uint32_t bDst = smem_u32(&Bs[0][0][0]) + bk * 144 + bc * 8;
    int aValid = (agr < M) ? 16 : 0;

    float acc[2][4][4];
    #pragma unroll
    for (int i = 0; i < 2; i++)
        #pragma unroll
        for (int j = 0; j < 4; j++)
            #pragma unroll
            for (int q = 0; q < 4; q++) acc[i][j][q] = 0.0f;

    int l15 = lane & 15;
    int lhi = lane >> 4;
    uint32_t sA = smem_u32(&As[0][0][0]);
    uint32_t sB = smem_u32(&Bs[0][0][0]);
    uint32_t aoff[2], boff[2];
    #pragma unroll
    for (int mt = 0; mt < 2; mt++)
        aoff[mt] = sA + (uint32_t)(((warp_m * 32 + mt * 16 + l15) * ASTRIDE + lhi * 8) * 2);
    #pragma unroll
    for (int p = 0; p < 2; p++)
        boff[p] = sB + (uint32_t)((l15 * BSTRIDE + warp_n * 32 + p * 16 + lhi * 8) * 2);

    auto issue = [&](int kt) {
        int stg = kt % ST;
        int k0 = kt * BK;
        uint32_t ad = aDst + stg * ABUF;
        uint32_t bd = bDst + stg * BBUF;
        asm volatile("cp.async.cg.shared.global [%0], [%1], 16, %2;"
                     :: "r"(ad), "l"(aSrcBase + k0), "r"(aValid));
        asm volatile("cp.async.ca.shared.global [%0], [%1], 8;"
                     :: "r"(bd), "l"(bSrcBase + (size_t)k0 * N));
        asm volatile("cp.async.commit_group;");
    };

    issue(0);
    issue(1);

    int KT = K / BK;
    for (int kt = 0; kt < KT; kt++) {
        if (kt == KT - 1) asm volatile("cp.async.wait_group 0;");
        else              asm volatile("cp.async.wait_group 1;");
        __syncthreads();
        if (kt + 2 < KT) issue(kt + 2);   // writes stage (kt-1)%3, freed by this sync

        int cur = kt % ST;
        uint32_t a[2][4], b[2][4];
        uint32_t bufA = cur * ABUF, bufB = cur * BBUF;
        #pragma unroll
        for (int mt = 0; mt < 2; mt++)
            LDSM_X4(a[mt][0], a[mt][1], a[mt][2], a[mt][3], aoff[mt] + bufA);
        #pragma unroll
        for (int p = 0; p < 2; p++)
            LDSM_X4_T(b[p][0], b[p][1], b[p][2], b[p][3], boff[p] + bufB);

        #pragma unroll
        for (int mt = 0; mt < 2; mt++)
            #pragma unroll
            for (int nt = 0; nt < 4; nt++) {
                uint32_t b0 = b[nt >> 1][(nt & 1) * 2];
                uint32_t b1 = b[nt >> 1][(nt & 1) * 2 + 1];
                asm volatile(
                    "mma.sync.aligned.m16n8k16.row.col.f32.f16.f16.f32 "
                    "{%0,%1,%2,%3}, {%4,%5,%6,%7}, {%8,%9}, {%0,%1,%2,%3};"
                    : "+f"(acc[mt][nt][0]), "+f"(acc[mt][nt][1]),
                      "+f"(acc[mt][nt][2]), "+f"(acc[mt][nt][3])
                    : "r"(a[mt][0]), "r"(a[mt][1]), "r"(a[mt][2]), "r"(a[mt][3]),
                      "r"(b0), "r"(b1));
            }
    }

    int g = lane >> 2;
    int tg = lane & 3;
    #pragma unroll
    for (int mt = 0; mt < 2; mt++) {
        int r0 = brow + warp_m * 32 + mt * 16 + g;
        int r1 = r0 + 8;
        #pragma unroll
        for (int nt = 0; nt < 4; nt++) {
            int cc = bcol + warp_n * 32 + nt * 8 + 2 * tg;
            if (r0 < M) {
                __half2 v = __floats2half2_rn(acc[mt][nt][0], acc[mt][nt][1]);
                *(__half2*)&Ch[(size_t)r0 * N + cc] = v;
            }
            if (r1 < M) {
                __half2 v = __floats2half2_rn(acc[mt][nt][2], acc[mt][nt][3]);
                *(__half2*)&Ch[(size_t)r1 * N + cc] = v;
            }
        }
    }
}

// ---------------- fused aggregate + self-loop + bias (+relu), node-chunked ----------------
__device__ __forceinline__ void fma8(float* acc, uint4 v, float w) {
    float2 f0 = __half22float2(*(__half2*)&v.x);
    float2 f1 = __half22float2(*(__half2*)&v.y);
    float2 f2 = __half22float2(*(__half2*)&v.z);
    float2 f3 = __half22float2(*(__half2*)&v.w);
    acc[0] = fmaf(f0.x, w, acc[0]); acc[1] = fmaf(f0.y, w, acc[1]);
    acc[2] = fmaf(f1.x, w, acc[2]); acc[3] = fmaf(f1.y, w, acc[3]);
    acc[4] = fmaf(f2.x, w, acc[4]); acc[5] = fmaf(f2.y, w, acc[5]);
    acc[6] = fmaf(f3.x, w, acc[6]); acc[7] = fmaf(f3.y, w, acc[7]);
}

template<int C, bool RELU, typename OUTT>
__global__ void aggregate_kernel(const __half* __restrict__ h,
                                 const float* __restrict__ bias,
                                 OUTT* __restrict__ out, int node0, int nnodes) {
    constexpr int TPN = C / 8;
    constexpr int NPB = 128 / TPN;
    int local = threadIdx.x / TPN;
    int c8 = threadIdx.x % TPN;
    int node = node0 + blockIdx.x * NPB + local;
    if (node >= node0 + nnodes) return;

    const uint4* h8 = (const uint4*)h;
    const size_t S = C / 8;
    int indeg = __ldg(&g_fill[node]);
    float d = rsqrtf((float)indeg + 1.0f);

    float acc[8] = {};
    fma8(acc, __ldg(&h8[(size_t)node * S + c8]), d);   // self-loop

    const int* slots = &g_slots[(size_t)node << SLOT_SHIFT];
    int p = 0;
    for (; p + 4 <= indeg; p += 4) {
        int s0 = __ldg(&slots[p]),     s1 = __ldg(&slots[p + 1]);
        int s2 = __ldg(&slots[p + 2]), s3 = __ldg(&slots[p + 3]);
        float w0 = __ldg(&g_dis[s0]),  w1 = __ldg(&g_dis[s1]);
        float w2 = __ldg(&g_dis[s2]),  w3 = __ldg(&g_dis[s3]);
        uint4 v0 = __ldg(&h8[(size_t)s0 * S + c8]);
        uint4 v1 = __ldg(&h8[(size_t)s1 * S + c8]);
        uint4 v2 = __ldg(&h8[(size_t)s2 * S + c8]);
        uint4 v3 = __ldg(&h8[(size_t)s3 * S + c8]);
        fma8(acc, v0, w0); fma8(acc, v1, w1); fma8(acc, v2, w2); fma8(acc, v3, w3);
    }
    for (; p < indeg; ++p) {
        int s = __ldg(&slots[p]);
        fma8(acc, __ldg(&h8[(size_t)s * S + c8]), __ldg(&g_dis[s]));
    }

    int colb = c8 * 8;
    float4 b0 = __ldg(&((const float4*)bias)[c8 * 2]);
    float4 b1 = __ldg(&((const float4*)bias)[c8 * 2 + 1]);
    float r[8];
    r[0] = fmaf(d, acc[0], b0.x); r[1] = fmaf(d, acc[1], b0.y);
    r[2] = fmaf(d, acc[2], b0.z); r[3] = fmaf(d, acc[3], b0.w);
    r[4] = fmaf(d, acc[4], b1.x); r[5] = fmaf(d, acc[5], b1.y);
    r[6] = fmaf(d, acc[6], b1.z); r[7] = fmaf(d, acc[7], b1.w);
    if (RELU) {
        #pragma unroll
        for (int i = 0; i < 8; i++) r[i] = fmaxf(r[i], 0.0f);
    }
    if constexpr (std::is_same<OUTT, __half>::value) {
        __half2 p0 = __floats2half2_rn(r[0], r[1]);
        __half2 p1 = __floats2half2_rn(r[2], r[3]);
        __half2 p2 = __floats2half2_rn(r[4], r[5]);
        __half2 p3 = __floats2half2_rn(r[6], r[7]);
        uint4 u;
        u.x = *(uint32_t*)&p0; u.y = *(uint32_t*)&p1;
        u.z = *(uint32_t*)&p2; u.w = *(uint32_t*)&p3;
        *(uint4*)&out[(size_t)node * C + colb] = u;
    } else {
        *(float4*)&out[(size_t)node * C + colb]     = make_float4(r[0], r[1], r[2], r[3]);
        *(float4*)&out[(size_t)node * C + colb + 4] = make_float4(r[4], r[5], r[6], r[7]);
    }
}

// ---------------- driver ----------------
static inline int cdiv(long long a, long long b) { return (int)((a + b - 1) / b); }

static cudaEvent_t make_event() {
    cudaEvent_t e;
    cudaEventCreateWithFlags(&e, cudaEventDisableTiming);
    return e;
}

extern "C" void kernel_launch(void* const* d_in, const int* in_sizes, int n_in,
                              void* d_out, int out_size) {
    const float* x  = (const float*)d_in[0];
    const float* W1 = (const float*)d_in[1];
    const float* b1 = (const float*)d_in[2];
    const float* W2 = (const float*)d_in[3];
    const float* b2 = (const float*)d_in[4];
    const float* W3 = (const float*)d_in[5];
    const float* b3 = (const float*)d_in[6];
    const int*   ei = (const int*)d_in[7];   // int32 (JAX default dtype demotion)
    int E = in_sizes[7] / 2;
    float* out = (float*)d_out;

    __half *h1, *h2, *t, *xh, *w1h, *w2h, *w3h;
    cudaGetSymbolAddress((void**)&h1,  g_h1);
    cudaGetSymbolAddress((void**)&h2,  g_h2);
    cudaGetSymbolAddress((void**)&t,   g_t);
    cudaGetSymbolAddress((void**)&xh,  g_xh);
    cudaGetSymbolAddress((void**)&w1h, g_w1h);
    cudaGetSymbolAddress((void**)&w2h, g_w2h);
    cudaGetSymbolAddress((void**)&w3h, g_w3h);

    // infrastructure handles (created on the eager correctness call, not during capture)
    static cudaStream_t s2 = [] {
        cudaStream_t s; cudaStreamCreateWithFlags(&s, cudaStreamNonBlocking); return s;
    }();
    static cudaEvent_t eFork = make_event();
    static cudaEvent_t eW1   = make_event();
    static cudaEvent_t eA    = make_event();
    static cudaEvent_t eB    = make_event();
    static cudaEvent_t eC0   = make_event();
    static cudaEvent_t eC1   = make_event();
    static cudaEvent_t eD0   = make_event();
    static cudaEvent_t eD1   = make_event();
    static cudaEvent_t eE    = make_event();

    const int TPB = 256;
    const int H = HALF_N;

    // ---- fork point ----
    cudaEventRecord(eFork, 0);
    cudaStreamWaitEvent(s2, eFork, 0);

    // ---- stream0: cvt w1 + x chunk0, gemm1 chunk0 ----
    cvt_kernel<<<cdiv(256 * 256 / 4, TPB), TPB>>>(W1, w1h, 256 * 256 / 4);
    cudaEventRecord(eW1, 0);
    cvt_kernel<<<cdiv(H * 256 / 4, TPB), TPB>>>(x, xh, H * 256 / 4);
    {
        dim3 grid(256 / 64, cdiv(H, 128));
        gemm_f16_kernel<<<grid, 256>>>(xh, w1h, h1, H, 256, 256);
    }
    cudaEventRecord(eA, 0);

    // ---- s2: prep, w2/w3 cvt, x chunk1 cvt, gemm1 chunk1 ----
    zero_fill_kernel<<<cdiv(N_NODES, TPB), TPB, 0, s2>>>();
    fill_kernel<<<cdiv(E, TPB), TPB, 0, s2>>>(ei, E);
    dis_kernel<<<cdiv(N_NODES, TPB), TPB, 0, s2>>>();
    cvt_kernel<<<cdiv(256 * 128 / 4, TPB), TPB, 0, s2>>>(W2, w2h, 256 * 128 / 4);
    cvt_kernel<<<cdiv(128 * 64 / 4, TPB), TPB, 0, s2>>>(W3, w3h, 128 * 64 / 4);
    cvt_kernel<<<cdiv(H * 256 / 4, TPB), TPB, 0, s2>>>(x + (size_t)H * 256,
                                                       xh + (size_t)H * 256, H * 256 / 4);
    cudaStreamWaitEvent(s2, eW1, 0);
    {
        dim3 grid(256 / 64, cdiv(H, 128));
        gemm_f16_kernel<<<grid, 256, 0, s2>>>(xh + (size_t)H * 256, w1h,
                                              h1 + (size_t)H * 256, H, 256, 256);
    }
    cudaEventRecord(eB, s2);

    // ---- pipelined layers: chunk 0 on stream 0, chunk 1 on s2 ----
    // layer 1 agg -> layer 2 gemm   (agg1 needs FULL h1: cross-wait)
    cudaStreamWaitEvent(0, eB, 0);
    aggregate_kernel<256, true, __half><<<cdiv(H, 4), 128>>>(h1, b1, t, 0, H);
    {
        dim3 grid(128 / 64, cdiv(H, 128));
        gemm_f16_kernel<<<grid, 256>>>(t, w2h, h2, H, 128, 256);
    }
    cudaEventRecord(eC0, 0);

    cudaStreamWaitEvent(s2, eA, 0);
    aggregate_kernel<256, true, __half><<<cdiv(H, 4), 128, 0, s2>>>(h1, b1, t, H, H);
    {
        dim3 grid(128 / 64, cdiv(H, 128));
        gemm_f16_kernel<<<grid, 256, 0, s2>>>(t + (size_t)H * 256, w2h,
                                              h2 + (size_t)H * 128, H, 128, 256);
    }
    cudaEventRecord(eC1, s2);

    // layer 2 agg -> layer 3 gemm
    cudaStreamWaitEvent(0, eC1, 0);
    aggregate_kernel<128, true, __half><<<cdiv(H, 8), 128>>>(h2, b2, t, 0, H);
    {
        dim3 grid(64 / 64, cdiv(H, 128));
        gemm_f16_kernel<<<grid, 256>>>(t, w3h, h1, H, 64, 128);
    }
    cudaEventRecord(eD0, 0);

    cudaStreamWaitEvent(s2, eC0, 0);
    aggregate_kernel<128, true, __half><<<cdiv(H, 8), 128, 0, s2>>>(h2, b2, t, H, H);
    {
        dim3 grid(64 / 64, cdiv(H, 128));
        gemm_f16_kernel<<<grid, 256, 0, s2>>>(t + (size_t)H * 128, w3h,
                                              h1 + (size_t)H * 64, H, 64, 128);
    }
    cudaEventRecord(eD1, s2);

    // layer 3 agg (final, fp32 out)
    cudaStreamWaitEvent(0, eD1, 0);
    aggregate_kernel<64, false, float><<<cdiv(H, 16), 128>>>(h1, b3, out, 0, H);

    cudaStreamWaitEvent(s2, eD0, 0);
    aggregate_kernel<64, false, float><<<cdiv(H, 16), 128, 0, s2>>>(h1, b3, out, H, H);
    cudaEventRecord(eE, s2);
    cudaStreamWaitEvent(0, eE, 0);
}